// round 2
// baseline (speedup 1.0000x reference)
#include <cuda_runtime.h>
#include <cuda_bf16.h>

// Problem constants (fixed by the dataset)
#define NNODES   100000
#define FIN      512
#define FHID     128
#define FOUT     40
#define NEDGES   3200000

// Scratch (device globals; no runtime allocation allowed)
__device__ __align__(256) float g_support1[(size_t)NNODES * FHID];  // X @ W1
__device__ __align__(256) float g_agg1[(size_t)NNODES * FHID];      // scatter-add result, layer 1
__device__ __align__(256) float g_support2[(size_t)NNODES * FOUT];  // relu(agg1+b1) @ W2
__device__ __align__(256) int   g_src[NEDGES];
__device__ __align__(256) int   g_dst[NEDGES];
__device__ int g_is64;

__device__ __forceinline__ void red_add_v4(float* p, float4 v) {
    asm volatile("red.global.add.v4.f32 [%0], {%1, %2, %3, %4};"
                 :: "l"(p), "f"(v.x), "f"(v.y), "f"(v.z), "f"(v.w)
                 : "memory");
}

// ---------------------------------------------------------------------------
// Edge-index dtype detection + decode.
// If the buffer holds genuine int64 values, the int64 view of the FIRST HALF
// (src array, E entries = byte range that is valid under both dtypes) is all
// in [0, N). If it holds int32, the int64 view fuses two random ids ->
// astronomically large values. One thread samples and records the verdict.
// ---------------------------------------------------------------------------
__global__ void detect_kernel(const void* ei, int E, int M) {
    const long long* p64 = (const long long*)ei;
    int ok64 = 1;
    // sample 4096 positions across [0, E) — all within the int32 footprint
    for (int i = 0; i < 4096; i++) {
        long long idx = (long long)i * (E / 4096);
        long long v = p64[idx];
        if (v < 0 || v >= M) { ok64 = 0; break; }
    }
    g_is64 = ok64;
}

__global__ void decode_kernel(const void* ei, int E, int M) {
    int e = blockIdx.x * blockDim.x + threadIdx.x;
    if (e >= E) return;
    int s, d;
    if (g_is64) {
        const long long* p = (const long long*)ei;
        s = (int)p[e];
        d = (int)p[(size_t)E + e];
    } else {
        const int* p = (const int*)ei;
        s = p[e];
        d = p[(size_t)E + e];
    }
    // defensive clamp: rel_err will expose any real index issue without IMA
    s = min(max(s, 0), M - 1);
    d = min(max(d, 0), M - 1);
    g_src[e] = s;
    g_dst[e] = d;
}

// ---------------------------------------------------------------------------
// Zero kernels (agg buffers must be zeroed each replay; d_out is poisoned)
// ---------------------------------------------------------------------------
__global__ void zero_agg1_kernel(int M) {
    size_t i = (size_t)blockIdx.x * blockDim.x + threadIdx.x;
    size_t n4 = (size_t)M * (FHID / 4);
    if (i < n4) ((float4*)g_agg1)[i] = make_float4(0.f, 0.f, 0.f, 0.f);
}

__global__ void zero_out_kernel(float* out, int M) {
    size_t i = (size_t)blockIdx.x * blockDim.x + threadIdx.x;
    size_t n4 = (size_t)M * (FOUT / 4);
    if (i < n4) ((float4*)out)[i] = make_float4(0.f, 0.f, 0.f, 0.f);
}

// ---------------------------------------------------------------------------
// GEMM1: support1 = X[M,512] @ W1[512,128]
// BM=128, BN=64, BK=16, TM=8, TN=4, 256 threads
// ---------------------------------------------------------------------------
#define G1_BM 128
#define G1_BN 64
#define G1_BK 16

__global__ __launch_bounds__(256) void gemm1_kernel(
    const float* __restrict__ A, const float* __restrict__ B, int M)
{
    __shared__ float As[G1_BK][G1_BM + 1];
    __shared__ float Bs[G1_BK][G1_BN];

    const int tid = threadIdx.x;
    const int blockRow = blockIdx.y * G1_BM;
    const int blockCol = blockIdx.x * G1_BN;

    const int tr = tid / 16;       // 0..15 -> 8 rows each
    const int tc = tid % 16;       // 0..15 -> 4 cols each

    float acc[8][4];
#pragma unroll
    for (int i = 0; i < 8; i++)
#pragma unroll
        for (int j = 0; j < 4; j++) acc[i][j] = 0.f;

    const int lbr = tid / 16;            // 0..15  (Bs row)
    const int lbc = (tid % 16) * 4;      // Bs col (float4)

    for (int k0 = 0; k0 < FIN; k0 += G1_BK) {
        // Load A tile: 128x16 = 512 float4, 2 per thread
#pragma unroll
        for (int l = 0; l < 2; l++) {
            int lin = tid + l * 256;
            int lar = lin / 4;             // 0..127
            int lac = (lin % 4) * 4;       // 0,4,8,12
            int gr = blockRow + lar;
            float4 av = make_float4(0.f, 0.f, 0.f, 0.f);
            if (gr < M)
                av = *(const float4*)(A + (size_t)gr * FIN + k0 + lac);
            As[lac + 0][lar] = av.x;
            As[lac + 1][lar] = av.y;
            As[lac + 2][lar] = av.z;
            As[lac + 3][lar] = av.w;
        }
        // Load B tile: 16x64 = 256 float4, 1 per thread
        {
            float4 bv = *(const float4*)(B + (size_t)(k0 + lbr) * FHID + blockCol + lbc);
            *(float4*)&Bs[lbr][lbc] = bv;
        }
        __syncthreads();

#pragma unroll
        for (int kk = 0; kk < G1_BK; kk++) {
            float a[8], b[4];
#pragma unroll
            for (int i = 0; i < 8; i++) a[i] = As[kk][tr * 8 + i];
#pragma unroll
            for (int j = 0; j < 4; j++) b[j] = Bs[kk][tc * 4 + j];
#pragma unroll
            for (int i = 0; i < 8; i++)
#pragma unroll
                for (int j = 0; j < 4; j++) acc[i][j] = fmaf(a[i], b[j], acc[i][j]);
        }
        __syncthreads();
    }

#pragma unroll
    for (int i = 0; i < 8; i++) {
        int gr = blockRow + tr * 8 + i;
        if (gr < M) {
            float4 v = make_float4(acc[i][0], acc[i][1], acc[i][2], acc[i][3]);
            *(float4*)(g_support1 + (size_t)gr * FHID + blockCol + tc * 4) = v;
        }
    }
}

// ---------------------------------------------------------------------------
// Scatter1: agg1[dst] += w * support1[src]  (128 floats/edge, warp per edge)
// ---------------------------------------------------------------------------
__global__ __launch_bounds__(256) void scatter1_kernel(
    const float* __restrict__ ew, int E)
{
    int warp = (int)(((size_t)blockIdx.x * blockDim.x + threadIdx.x) >> 5);
    int lane = threadIdx.x & 31;
    if (warp >= E) return;

    int s = g_src[warp];
    int d = g_dst[warp];
    float w = ew[warp];

    float4 v = ((const float4*)(g_support1 + (size_t)s * FHID))[lane];
    v.x *= w; v.y *= w; v.z *= w; v.w *= w;
    red_add_v4((float*)(((float4*)(g_agg1 + (size_t)d * FHID)) + lane), v);
}

// ---------------------------------------------------------------------------
// GEMM2 (fused bias+relu on the input load):
//   support2 = relu(agg1 + b1) @ W2[128,40]
// Block handles 32 rows; W2 (20 KB) + X tile (16 KB) in smem.
// ---------------------------------------------------------------------------
__global__ __launch_bounds__(256) void gemm2_kernel(
    const float* __restrict__ W2, const float* __restrict__ b1, int M)
{
    __shared__ float Ws[FHID * FOUT];   // 5120 floats
    __shared__ float Xs[32 * FHID];     // 4096 floats

    const int tid = threadIdx.x;
    const int row0 = blockIdx.x * 32;

    for (int i = tid; i < FHID * FOUT; i += 256) Ws[i] = W2[i];

    // Load + fuse bias/relu: 32 rows x 128 = 1024 float4
    for (int i = tid; i < 1024; i += 256) {
        int r = i >> 5;
        int c4 = (i & 31) * 4;
        int gr = row0 + r;
        float4 v = make_float4(0.f, 0.f, 0.f, 0.f);
        if (gr < M) {
            v = *(const float4*)(g_agg1 + (size_t)gr * FHID + c4);
            v.x = fmaxf(v.x + b1[c4 + 0], 0.f);
            v.y = fmaxf(v.y + b1[c4 + 1], 0.f);
            v.z = fmaxf(v.z + b1[c4 + 2], 0.f);
            v.w = fmaxf(v.w + b1[c4 + 3], 0.f);
        }
        *(float4*)&Xs[r * FHID + c4] = v;
    }
    __syncthreads();

    for (int o = tid; o < 32 * FOUT; o += 256) {
        int r = o / FOUT;
        int c = o % FOUT;
        float acc = 0.f;
        const float* xr = &Xs[r * FHID];
#pragma unroll 8
        for (int k = 0; k < FHID; k++) acc = fmaf(xr[k], Ws[k * FOUT + c], acc);
        int gr = row0 + r;
        if (gr < M) g_support2[(size_t)gr * FOUT + c] = acc;
    }
}

// ---------------------------------------------------------------------------
// Scatter2: out[dst] += w * support2[src]  (40 floats/edge = 10 float4 chunks)
// One thread per (edge, chunk).
// ---------------------------------------------------------------------------
__global__ __launch_bounds__(256) void scatter2_kernel(
    const float* __restrict__ ew, float* __restrict__ out, int E)
{
    size_t idx = (size_t)blockIdx.x * blockDim.x + threadIdx.x;
    size_t total = (size_t)E * 10;
    if (idx >= total) return;
    int e = (int)(idx / 10);
    int c = (int)(idx - (size_t)e * 10);

    int s = g_src[e];
    int d = g_dst[e];
    float w = ew[e];

    float4 v = *(const float4*)(g_support2 + (size_t)s * FOUT + c * 4);
    v.x *= w; v.y *= w; v.z *= w; v.w *= w;
    red_add_v4(out + (size_t)d * FOUT + c * 4, v);
}

// ---------------------------------------------------------------------------
// log_softmax over 40 cols (+ b2), warp per row, in-place on d_out
// ---------------------------------------------------------------------------
__global__ __launch_bounds__(256) void lsm_kernel(
    float* __restrict__ out, const float* __restrict__ b2, int M)
{
    int row = (int)(((size_t)blockIdx.x * blockDim.x + threadIdx.x) >> 5);
    if (row >= M) return;
    int lane = threadIdx.x & 31;

    float* p = out + (size_t)row * FOUT;
    float v0 = p[lane] + b2[lane];
    float v1 = -3.0e38f;
    if (lane < 8) v1 = p[32 + lane] + b2[32 + lane];

    float m = fmaxf(v0, v1);
#pragma unroll
    for (int o = 16; o; o >>= 1) m = fmaxf(m, __shfl_xor_sync(0xffffffffu, m, o));

    float s = __expf(v0 - m) + ((lane < 8) ? __expf(v1 - m) : 0.f);
#pragma unroll
    for (int o = 16; o; o >>= 1) s += __shfl_xor_sync(0xffffffffu, s, o);

    float l = m + __logf(s);
    p[lane] = v0 - l;
    if (lane < 8) p[32 + lane] = v1 - l;
}

// ---------------------------------------------------------------------------
// Launch
// ---------------------------------------------------------------------------
extern "C" void kernel_launch(void* const* d_in, const int* in_sizes, int n_in,
                              void* d_out, int out_size)
{
    const float* x   = (const float*)d_in[0];
    const void*  ei  = d_in[1];
    const float* ew  = (const float*)d_in[2];
    const float* W1  = (const float*)d_in[3];
    const float* b1  = (const float*)d_in[4];
    const float* W2  = (const float*)d_in[5];
    const float* b2  = (const float*)d_in[6];
    float* out = (float*)d_out;

    const int M = in_sizes[0] / FIN;     // 100000
    const int E = in_sizes[2];           // 3200000 (edge_w element count)

    // Edge index dtype detect + decode into int32 src/dst
    detect_kernel<<<1, 1>>>(ei, E, M);
    decode_kernel<<<(E + 255) / 256, 256>>>(ei, E, M);

    // Zero accumulators (replayed every graph launch)
    {
        size_t n4 = (size_t)M * (FHID / 4);
        zero_agg1_kernel<<<(unsigned)((n4 + 255) / 256), 256>>>(M);
        size_t o4 = (size_t)M * (FOUT / 4);
        zero_out_kernel<<<(unsigned)((o4 + 255) / 256), 256>>>(out, M);
    }

    // Layer 1 GEMM
    {
        dim3 grid(FHID / G1_BN, (M + G1_BM - 1) / G1_BM);
        gemm1_kernel<<<grid, 256>>>(x, W1, M);
    }

    // Layer 1 scatter-add
    {
        int blocks = (E + 7) / 8;   // 8 warps/block, 1 warp/edge
        scatter1_kernel<<<blocks, 256>>>(ew, E);
    }

    // Layer 2 GEMM (fused bias+relu on load)
    {
        int blocks = (M + 31) / 32;
        gemm2_kernel<<<blocks, 256>>>(W2, b1, M);
    }

    // Layer 2 scatter-add into d_out
    {
        size_t total = (size_t)E * 10;
        scatter2_kernel<<<(unsigned)((total + 255) / 256), 256>>>(ew, out, E);
    }

    // log_softmax (+b2), warp per row
    {
        int rowsPerBlock = 256 / 32;
        lsm_kernel<<<(M + rowsPerBlock - 1) / rowsPerBlock, 256>>>(out, b2, M);
    }
}